// round 15
// baseline (speedup 1.0000x reference)
#include <cuda_runtime.h>
#include <cuda_bf16.h>
#include <math.h>
#include <stdint.h>

#define NN 100000
#define EE 400000
#define ET (EE + NN)
#define GG 4000
#define FIN 32
#define HIDC 128
#define HH 3
#define W3C 384
#define NCLS 10
#define NLAY 4
#define NB1 ((NN + 511) / 512)

// ---------------- device scratch ----------------
__device__ float d_bufB[(size_t)NN * W3C];   // HW = x @ W (fp32, aggregation gather)
__device__ __nv_bfloat16 d_axhi[(size_t)NN * 256];
__device__ __nv_bfloat16 d_axlo[(size_t)NN * 256];
__device__ __nv_bfloat16 d_ayhi[(size_t)NN * W3C];
__device__ __nv_bfloat16 d_aylo[(size_t)NN * W3C];
__device__ __nv_bfloat16 d_wthi[W3C * W3C];
__device__ __nv_bfloat16 d_wtlo[W3C * W3C];
__device__ float d_es[NN * HH];
__device__ float d_ed[NN * HH];
__device__ float d_scale[W3C];
__device__ float d_shift[W3C];
__device__ float d_tmod[W3C];
__device__ float d_bnsum[W3C];
__device__ float d_bnsq[W3C];
__device__ float d_gs[(size_t)GG * W3C];
__device__ float d_gh[(size_t)GG * HIDC];
__device__ float d_logits[GG * NCLS];
// CSR + graph offsets
__device__ int d_deg[NN];
__device__ int d_off[NN + 1];
__device__ int d_cur[NN];
__device__ int d_csrc[ET];
__device__ int d_part[256];
__device__ int d_goff[GG + 1];

// ---------------- low-level helpers ----------------
__device__ __forceinline__ void cp16(void* dst, const void* src, int bytes)
{
    unsigned int d = (unsigned int)__cvta_generic_to_shared(dst);
    asm volatile("cp.async.ca.shared.global [%0], [%1], 16, %2;" :: "r"(d), "l"(src), "r"(bytes));
}

__device__ __forceinline__ uint32_t smem_u32(const void* p)
{
    uint32_t a;
    asm("{ .reg .u64 t; cvta.to.shared.u64 t, %1; cvt.u32.u64 %0, t; }" : "=r"(a) : "l"(p));
    return a;
}

__device__ __forceinline__ void ldsm4(uint32_t& r0, uint32_t& r1, uint32_t& r2, uint32_t& r3,
                                      uint32_t addr)
{
    asm volatile("ldmatrix.sync.aligned.m8n8.x4.shared.b16 {%0,%1,%2,%3}, [%4];"
                 : "=r"(r0), "=r"(r1), "=r"(r2), "=r"(r3) : "r"(addr));
}
__device__ __forceinline__ void ldsm2(uint32_t& r0, uint32_t& r1, uint32_t addr)
{
    asm volatile("ldmatrix.sync.aligned.m8n8.x2.shared.b16 {%0,%1}, [%2];"
                 : "=r"(r0), "=r"(r1) : "r"(addr));
}

__device__ __forceinline__ void mma16816(float* c, const uint32_t* a, const uint32_t* b)
{
    asm volatile(
        "mma.sync.aligned.m16n8k16.row.col.f32.bf16.bf16.f32 "
        "{%0,%1,%2,%3}, {%4,%5,%6,%7}, {%8,%9}, {%0,%1,%2,%3};"
        : "+f"(c[0]), "+f"(c[1]), "+f"(c[2]), "+f"(c[3])
        : "r"(a[0]), "r"(a[1]), "r"(a[2]), "r"(a[3]), "r"(b[0]), "r"(b[1]));
}

// ---------------- split-bf16 tensor-core GEMM (2 CTAs/SM) -------------------
__global__ void __launch_bounds__(256, 2) mma_gemm(
    const __nv_bfloat16* __restrict__ ahi, const __nv_bfloat16* __restrict__ alo,
    const __nv_bfloat16* __restrict__ bthi, const __nv_bfloat16* __restrict__ btlo,
    const float* __restrict__ bias, float* __restrict__ outF,
    int M, int N, int K, int relu,
    __nv_bfloat16* __restrict__ oh, __nv_bfloat16* __restrict__ ol)
{
    extern __shared__ char smem[];
    const int MAT = 10240;
    const int ST = 4 * MAT;
    int tid = threadIdx.x;
    int warp = tid >> 5, lane = tid & 31;
    int wm = warp >> 2, wn = warp & 3;
    int bm = blockIdx.y * 128, bn = blockIdx.x * 128;

    float acc[4][4][4];
#pragma unroll
    for (int i = 0; i < 4; i++)
#pragma unroll
        for (int j = 0; j < 4; j++)
#pragma unroll
            for (int r = 0; r < 4; r++) acc[i][j][r] = 0.f;

    const int nk = K >> 5;

    auto load_stage = [&](int s, int k0) {
        char* base = smem + s * ST;
#pragma unroll
        for (int t = 0; t < 8; t++) {
            int q = tid + t * 256;
            int sel = q >> 9;
            int r = q & 511;
            int row = r >> 2, ch = r & 3;
            char* dst = base + sel * MAT + row * 80 + ch * 16;
            if (sel < 2) {
                int gm = bm + row;
                const __nv_bfloat16* src = (sel == 0 ? ahi : alo);
                const __nv_bfloat16* p = src + (size_t)(gm < M ? gm : 0) * K + k0 + ch * 8;
                cp16(dst, p, gm < M ? 16 : 0);
            } else {
                int gn = bn + row;
                const __nv_bfloat16* src = (sel == 2 ? bthi : btlo);
                cp16(dst, src + (size_t)gn * K + k0 + ch * 8, 16);
            }
        }
        asm volatile("cp.async.commit_group;");
    };

    load_stage(0, 0);
    for (int t = 0; t < nk; t++) {
        if (t + 1 < nk) {
            load_stage((t + 1) & 1, (t + 1) << 5);
            asm volatile("cp.async.wait_group 1;");
        } else {
            asm volatile("cp.async.wait_group 0;");
        }
        __syncthreads();
        uint32_t sb = smem_u32(smem + (t & 1) * ST);
#pragma unroll
        for (int ks = 0; ks < 2; ks++) {
            int k0 = ks * 16;
            uint32_t af[2][4][4];
            uint32_t bf[2][4][2];
#pragma unroll
            for (int mt = 0; mt < 4; mt++) {
                int row = wm * 64 + mt * 16 + (lane & 15);
                uint32_t off = row * 80 + (k0 + (lane >> 4) * 8) * 2;
                ldsm4(af[0][mt][0], af[0][mt][1], af[0][mt][2], af[0][mt][3], sb + off);
                ldsm4(af[1][mt][0], af[1][mt][1], af[1][mt][2], af[1][mt][3], sb + MAT + off);
            }
#pragma unroll
            for (int nt = 0; nt < 4; nt++) {
                int row = wn * 32 + nt * 8 + (lane & 7);
                uint32_t off = row * 80 + (k0 + ((lane >> 3) & 1) * 8) * 2;
                ldsm2(bf[0][nt][0], bf[0][nt][1], sb + 2 * MAT + off);
                ldsm2(bf[1][nt][0], bf[1][nt][1], sb + 3 * MAT + off);
            }
#pragma unroll
            for (int mt = 0; mt < 4; mt++)
#pragma unroll
                for (int nt = 0; nt < 4; nt++) {
                    mma16816(acc[mt][nt], af[0][mt], bf[0][nt]);
                    mma16816(acc[mt][nt], af[0][mt], bf[1][nt]);
                    mma16816(acc[mt][nt], af[1][mt], bf[0][nt]);
                }
        }
        __syncthreads();
    }

    int g = lane >> 2, c2 = (lane & 3) * 2;
#pragma unroll
    for (int mt = 0; mt < 4; mt++) {
        int m0 = bm + wm * 64 + mt * 16 + g;
#pragma unroll
        for (int half = 0; half < 2; half++) {
            int m = m0 + half * 8;
            if (m >= M) continue;
#pragma unroll
            for (int nt = 0; nt < 4; nt++) {
                int n = bn + wn * 32 + nt * 8 + c2;
                float v0 = acc[mt][nt][half * 2 + 0];
                float v1 = acc[mt][nt][half * 2 + 1];
                if (bias) { v0 += bias[n]; v1 += bias[n + 1]; }
                if (relu) { v0 = fmaxf(v0, 0.f); v1 = fmaxf(v1, 0.f); }
                if (outF) *(float2*)&outF[(size_t)m * N + n] = make_float2(v0, v1);
                if (oh) {
                    __nv_bfloat16 h0 = __float2bfloat16(v0);
                    __nv_bfloat16 h1 = __float2bfloat16(v1);
                    __nv_bfloat162 hp; hp.x = h0; hp.y = h1;
                    __nv_bfloat162 lp;
                    lp.x = __float2bfloat16(v0 - __bfloat162float(h0));
                    lp.y = __float2bfloat16(v1 - __bfloat162float(h1));
                    *(__nv_bfloat162*)&oh[(size_t)m * N + n] = hp;
                    *(__nv_bfloat162*)&ol[(size_t)m * N + n] = lp;
                }
            }
        }
    }
}

// ---------------- transpose + scale + split weights -------------------------
__global__ void transpose_split(const float* __restrict__ W, const float* __restrict__ scale,
                                int K, int N)
{
    int idx = blockIdx.x * blockDim.x + threadIdx.x;
    if (idx >= K * N) return;
    int k = idx / N, n = idx - k * N;
    float v = W[idx];
    if (scale) v *= scale[k];
    __nv_bfloat16 h = __float2bfloat16(v);
    d_wthi[(size_t)n * K + k] = h;
    d_wtlo[(size_t)n * K + k] = __float2bfloat16(v - __bfloat162float(h));
}

// ---------------- f32x2 helpers ----------------
__device__ __forceinline__ unsigned long long pack2(float x, float y)
{
    unsigned long long r;
    asm("mov.b64 %0, {%1, %2};" : "=l"(r) : "r"(__float_as_uint(x)), "r"(__float_as_uint(y)));
    return r;
}
__device__ __forceinline__ unsigned long long fma2(unsigned long long a,
                                                   unsigned long long b,
                                                   unsigned long long c)
{
    unsigned long long d;
    asm("fma.rn.f32x2 %0, %1, %2, %3;" : "=l"(d) : "l"(a), "l"(b), "l"(c));
    return d;
}
__device__ __forceinline__ void unpack2(unsigned long long v, float& lo, float& hi)
{
    unsigned int a, b;
    asm("mov.b64 {%0, %1}, %2;" : "=r"(a), "=r"(b) : "l"(v));
    lo = __uint_as_float(a); hi = __uint_as_float(b);
}

// ---------------- pipelined fp32 SGEMM (stem lin1, head lin3) ---------------
__global__ void sgemm_pipe(const float* __restrict__ A, const float* __restrict__ B,
                           const float* __restrict__ bias, float* __restrict__ C,
                           int M, int Ncol, int K, int relu,
                           __nv_bfloat16* __restrict__ oh, __nv_bfloat16* __restrict__ ol)
{
    __shared__ float As[2][128][16];
    __shared__ float Bs[2][16][128];
    int tid = threadIdx.x;
    int tx = tid & 15, ty = tid >> 4;
    int bm = blockIdx.y * 128, bn = blockIdx.x * 128;

    unsigned long long acc[8][4];
#pragma unroll
    for (int i = 0; i < 8; i++)
#pragma unroll
        for (int j = 0; j < 4; j++) acc[i][j] = 0ull;

    const int nk = K >> 4;

    auto load_stage = [&](int s, int k0) {
#pragma unroll
        for (int t = 0; t < 2; t++) {
            int q = tid + t * 256;
            int m = q >> 2, kc = (q & 3) * 4;
            int gm = bm + m;
            int ok = (gm < M);
            const float* src = A + (size_t)(ok ? gm : 0) * K + k0 + kc;
            cp16(&As[s][m][kc], src, ok ? 16 : 0);
        }
#pragma unroll
        for (int t = 0; t < 2; t++) {
            int q = tid + t * 256;
            int kq = q >> 5, n4 = (q & 31) * 4;
            const float* src = B + (size_t)(k0 + kq) * Ncol + bn + n4;
            cp16(&Bs[s][kq][n4], src, 16);
        }
        asm volatile("cp.async.commit_group;");
    };

    load_stage(0, 0);
    for (int t = 0; t < nk; t++) {
        if (t + 1 < nk) {
            load_stage((t + 1) & 1, (t + 1) << 4);
            asm volatile("cp.async.wait_group 1;");
        } else {
            asm volatile("cp.async.wait_group 0;");
        }
        __syncthreads();
        int s = t & 1;
#pragma unroll
        for (int k4 = 0; k4 < 4; k4++) {
            float4 a[8];
#pragma unroll
            for (int i = 0; i < 8; i++)
                a[i] = *(const float4*)&As[s][ty + i * 16][k4 * 4];
#pragma unroll
            for (int kk = 0; kk < 4; kk++) {
                int k = k4 * 4 + kk;
                ulonglong2 b0 = *(const ulonglong2*)&Bs[s][k][tx * 8];
                ulonglong2 b1 = *(const ulonglong2*)&Bs[s][k][tx * 8 + 4];
                unsigned long long bp[4] = { b0.x, b0.y, b1.x, b1.y };
#pragma unroll
                for (int i = 0; i < 8; i++) {
                    float av = (&a[i].x)[kk];
                    unsigned long long ap = pack2(av, av);
#pragma unroll
                    for (int j = 0; j < 4; j++) acc[i][j] = fma2(ap, bp[j], acc[i][j]);
                }
            }
        }
        __syncthreads();
    }

#pragma unroll
    for (int i = 0; i < 8; i++) {
        int m = bm + ty + i * 16;
        if (m >= M) continue;
        float out[8];
#pragma unroll
        for (int j = 0; j < 4; j++) unpack2(acc[i][j], out[j * 2], out[j * 2 + 1]);
#pragma unroll
        for (int j = 0; j < 8; j++) {
            int n = bn + tx * 8 + j;
            float v = out[j];
            if (bias) v += bias[n];
            if (relu) v = fmaxf(v, 0.f);
            if (C) C[(size_t)m * Ncol + n] = v;
            if (oh) {
                __nv_bfloat16 h = __float2bfloat16(v);
                oh[(size_t)m * Ncol + n] = h;
                ol[(size_t)m * Ncol + n] = __float2bfloat16(v - __bfloat162float(h));
            }
        }
    }
}

// ---------------- small fallback GEMM ---------------------------------------
__global__ void sgemm_small(const float* __restrict__ A, const float* __restrict__ B,
                            const float* __restrict__ bias, float* __restrict__ C,
                            int M, int Ncol, int K, int relu)
{
    int m = blockIdx.x * blockDim.y + threadIdx.y;
    int n = threadIdx.x;
    if (m >= M || n >= Ncol) return;
    float s = 0.f;
    for (int k = 0; k < K; k++) s += A[(size_t)m * K + k] * B[(size_t)k * Ncol + n];
    if (bias) s += bias[n];
    if (relu) s = fmaxf(s, 0.f);
    C[(size_t)m * Ncol + n] = s;
}

// ---------------- CSR construction ------------------------------------------
__global__ void deg_count(const int* __restrict__ ei)
{
    int e = blockIdx.x * blockDim.x + threadIdx.x;
    if (e >= ET) return;
    int d = (e < EE) ? ei[EE + e] : (e - EE);
    atomicAdd(&d_deg[d], 1);
}

__global__ void scan_block()
{
    __shared__ int sh[512];
    int i = blockIdx.x * 512 + threadIdx.x;
    int v = (i < NN) ? d_deg[i] : 0;
    sh[threadIdx.x] = v;
    __syncthreads();
    for (int o = 1; o < 512; o <<= 1) {
        int t = (threadIdx.x >= o) ? sh[threadIdx.x - o] : 0;
        __syncthreads();
        sh[threadIdx.x] += t;
        __syncthreads();
    }
    if (i < NN) d_off[i] = sh[threadIdx.x] - v;
    if (threadIdx.x == 511) d_part[blockIdx.x] = sh[511];
}

__global__ void scan_part()
{
    __shared__ int sh[256];
    int t = threadIdx.x;
    int v = (t < NB1) ? d_part[t] : 0;
    sh[t] = v;
    __syncthreads();
    for (int o = 1; o < 256; o <<= 1) {
        int u = (t >= o) ? sh[t - o] : 0;
        __syncthreads();
        sh[t] += u;
        __syncthreads();
    }
    if (t < NB1) d_part[t] = sh[t] - v;
}

__global__ void scan_add()
{
    int i = blockIdx.x * blockDim.x + threadIdx.x;
    if (i < NN) {
        int v = d_off[i] + d_part[i >> 9];
        d_off[i] = v;
        d_cur[i] = v;
    }
    if (i == 0) d_off[NN] = ET;
}

__global__ void csr_scatter(const int* __restrict__ ei)
{
    int e = blockIdx.x * blockDim.x + threadIdx.x;
    if (e >= ET) return;
    int s = (e < EE) ? ei[e] : (e - EE);
    int d = (e < EE) ? ei[EE + e] : (e - EE);
    int pos = atomicAdd(&d_cur[d], 1);
    d_csrc[pos] = s;
}

// ---------------- graph offsets (batch is sorted) ---------------------------
__global__ void graph_off(const int* __restrict__ batch)
{
    int g = blockIdx.x * blockDim.x + threadIdx.x;
    if (g > GG) return;
    if (g == GG) { d_goff[GG] = NN; return; }
    int lo = 0, hi = NN;
    while (lo < hi) {
        int mid = (lo + hi) >> 1;
        if (batch[mid] < g) lo = mid + 1; else hi = mid;
    }
    d_goff[g] = lo;
}

// ---------------- GAT attention scores (warp per node, float4) --------------
__global__ void gat_scores(const float* __restrict__ HW,
                           const float* __restrict__ asrc,
                           const float* __restrict__ adst)
{
    int warp = (blockIdx.x * blockDim.x + threadIdx.x) >> 5;
    int lane = threadIdx.x & 31;
    if (warp >= NN) return;
    const float4* row = (const float4*)&HW[(size_t)warp * W3C];
    const float4* a4 = (const float4*)asrc;
    const float4* d4 = (const float4*)adst;
    float sa[3], sd[3];
#pragma unroll
    for (int t = 0; t < 3; t++) {
        float4 v = row[lane + 32 * t];
        float4 av = __ldg(&a4[lane + 32 * t]);
        float4 dv = __ldg(&d4[lane + 32 * t]);
        sa[t] = v.x * av.x + v.y * av.y + v.z * av.z + v.w * av.w;
        sd[t] = v.x * dv.x + v.y * dv.y + v.z * dv.z + v.w * dv.w;
    }
#pragma unroll
    for (int o = 16; o > 0; o >>= 1) {
#pragma unroll
        for (int t = 0; t < 3; t++) {
            sa[t] += __shfl_down_sync(0xffffffffu, sa[t], o);
            sd[t] += __shfl_down_sync(0xffffffffu, sd[t], o);
        }
    }
    if (lane == 0) {
#pragma unroll
        for (int t = 0; t < 3; t++) {
            d_es[warp * HH + t] = sa[t];
            d_ed[warp * HH + t] = sd[t];
        }
    }
}

// ---------------- fused segment softmax + aggregate + BN stats --------------
__global__ void gat_aggregate(const float* __restrict__ bias)
{
    __shared__ float bnS[W3C], bnQ[W3C];
    int tid = threadIdx.x;
    for (int c = tid; c < W3C; c += 256) { bnS[c] = 0.f; bnQ[c] = 0.f; }
    __syncthreads();

    int warp = (blockIdx.x * 256 + tid) >> 5;
    int lane = tid & 31;
    bool active = (warp < NN);

    if (active) {
        int beg = d_off[warp], end = d_off[warp + 1];
        int deg = end - beg;

        float edh0 = d_ed[warp * HH + 0];
        float edh1 = d_ed[warp * HH + 1];
        float edh2 = d_ed[warp * HH + 2];

        int sreg = 0;
        float xr0 = -INFINITY, xr1 = -INFINITY, xr2 = -INFINITY;
        if (lane < deg) {
            sreg = d_csrc[beg + lane];
            float a0 = d_es[sreg * HH + 0] + edh0;
            float a1 = d_es[sreg * HH + 1] + edh1;
            float a2 = d_es[sreg * HH + 2] + edh2;
            xr0 = (a0 > 0.f) ? a0 : 0.2f * a0;
            xr1 = (a1 > 0.f) ? a1 : 0.2f * a1;
            xr2 = (a2 > 0.f) ? a2 : 0.2f * a2;
        }
        float m0 = xr0, m1 = xr1, m2 = xr2;
        for (int j = beg + 32 + lane; j < end; j += 32) {
            int s = d_csrc[j];
            float a0 = d_es[s * HH + 0] + edh0; a0 = (a0 > 0.f) ? a0 : 0.2f * a0;
            float a1 = d_es[s * HH + 1] + edh1; a1 = (a1 > 0.f) ? a1 : 0.2f * a1;
            float a2 = d_es[s * HH + 2] + edh2; a2 = (a2 > 0.f) ? a2 : 0.2f * a2;
            m0 = fmaxf(m0, a0); m1 = fmaxf(m1, a1); m2 = fmaxf(m2, a2);
        }
#pragma unroll
        for (int o = 16; o > 0; o >>= 1) {
            m0 = fmaxf(m0, __shfl_xor_sync(0xffffffffu, m0, o));
            m1 = fmaxf(m1, __shfl_xor_sync(0xffffffffu, m1, o));
            m2 = fmaxf(m2, __shfl_xor_sync(0xffffffffu, m2, o));
        }

        float acc[3][4];
#pragma unroll
        for (int t = 0; t < 3; t++)
#pragma unroll
            for (int q = 0; q < 4; q++) acc[t][q] = 0.f;
        float s0 = 0.f, s1 = 0.f, s2 = 0.f;

        const float4* B4 = (const float4*)d_bufB;
        int n2 = deg < 32 ? deg : 32;
        for (int jj = 0; jj < n2; jj++) {
            int s = __shfl_sync(0xffffffffu, sreg, jj);
            float x0 = __shfl_sync(0xffffffffu, xr0, jj);
            float x1 = __shfl_sync(0xffffffffu, xr1, jj);
            float x2 = __shfl_sync(0xffffffffu, xr2, jj);
            float p0 = expf(x0 - m0), p1 = expf(x1 - m1), p2 = expf(x2 - m2);
            s0 += p0; s1 += p1; s2 += p2;
            const float4* row = B4 + (size_t)s * 96;
            float4 v0 = row[lane];
            float4 v1 = row[lane + 32];
            float4 v2 = row[lane + 64];
            acc[0][0] += p0 * v0.x; acc[0][1] += p0 * v0.y; acc[0][2] += p0 * v0.z; acc[0][3] += p0 * v0.w;
            acc[1][0] += p1 * v1.x; acc[1][1] += p1 * v1.y; acc[1][2] += p1 * v1.z; acc[1][3] += p1 * v1.w;
            acc[2][0] += p2 * v2.x; acc[2][1] += p2 * v2.y; acc[2][2] += p2 * v2.z; acc[2][3] += p2 * v2.w;
        }
        for (int j = beg + 32; j < end; j++) {
            int s = d_csrc[j];
            float a0 = d_es[s * HH + 0] + edh0; a0 = (a0 > 0.f) ? a0 : 0.2f * a0;
            float a1 = d_es[s * HH + 1] + edh1; a1 = (a1 > 0.f) ? a1 : 0.2f * a1;
            float a2 = d_es[s * HH + 2] + edh2; a2 = (a2 > 0.f) ? a2 : 0.2f * a2;
            float p0 = expf(a0 - m0), p1 = expf(a1 - m1), p2 = expf(a2 - m2);
            s0 += p0; s1 += p1; s2 += p2;
            const float4* row = B4 + (size_t)s * 96;
            float4 v0 = row[lane];
            float4 v1 = row[lane + 32];
            float4 v2 = row[lane + 64];
            acc[0][0] += p0 * v0.x; acc[0][1] += p0 * v0.y; acc[0][2] += p0 * v0.z; acc[0][3] += p0 * v0.w;
            acc[1][0] += p1 * v1.x; acc[1][1] += p1 * v1.y; acc[1][2] += p1 * v1.z; acc[1][3] += p1 * v1.w;
            acc[2][0] += p2 * v2.x; acc[2][1] += p2 * v2.y; acc[2][2] += p2 * v2.z; acc[2][3] += p2 * v2.w;
        }

        float inv[3] = { 1.f / s0, 1.f / s1, 1.f / s2 };
        const float4* b4 = (const float4*)bias;
        __nv_bfloat16* ohp = &d_ayhi[(size_t)warp * W3C];
        __nv_bfloat16* olp = &d_aylo[(size_t)warp * W3C];
#pragma unroll
        for (int t = 0; t < 3; t++) {
            float4 bv = __ldg(&b4[t * 32 + lane]);
            float v[4];
            v[0] = acc[t][0] * inv[t] + bv.x;
            v[1] = acc[t][1] * inv[t] + bv.y;
            v[2] = acc[t][2] * inv[t] + bv.z;
            v[3] = acc[t][3] * inv[t] + bv.w;
            int c = t * HIDC + 4 * lane;
#pragma unroll
            for (int q = 0; q < 4; q += 2) {
                __nv_bfloat16 h0 = __float2bfloat16(v[q]);
                __nv_bfloat16 h1 = __float2bfloat16(v[q + 1]);
                __nv_bfloat162 hp; hp.x = h0; hp.y = h1;
                __nv_bfloat162 lp;
                lp.x = __float2bfloat16(v[q] - __bfloat162float(h0));
                lp.y = __float2bfloat16(v[q + 1] - __bfloat162float(h1));
                *(__nv_bfloat162*)&ohp[c + q] = hp;
                *(__nv_bfloat162*)&olp[c + q] = lp;
            }
#pragma unroll
            for (int q = 0; q < 4; q++) {
                atomicAdd(&bnS[c + q], v[q]);
                atomicAdd(&bnQ[c + q], v[q] * v[q]);
            }
        }
    }

    __syncthreads();
    for (int c = tid; c < W3C; c += 256) {
        atomicAdd(&d_bnsum[c], bnS[c]);
        atomicAdd(&d_bnsq[c], bnQ[c]);
    }
}

// ---------------- BN finalize + zero-stats + fold shift into next bias ------
// W == nullptr for the last layer (no tmod needed).
__global__ void bn_fold(const float* __restrict__ gamma, const float* __restrict__ beta,
                        const float* __restrict__ W)
{
    __shared__ float sh[W3C];
    int c = threadIdx.x;  // 384
    float mu = d_bnsum[c] / (float)NN;
    float var = d_bnsq[c] / (float)NN - mu * mu;
    float sc = rsqrtf(var + 1e-5f) * gamma[c];
    float shf = beta[c] - mu * sc;
    d_scale[c] = sc;
    d_shift[c] = shf;
    d_bnsum[c] = 0.f;         // re-zero for next layer
    d_bnsq[c] = 0.f;
    sh[c] = shf;
    __syncthreads();
    if (W) {
        float s = 0.f;
        for (int k = 0; k < W3C; k++) s += sh[k] * W[(size_t)k * W3C + c];
        d_tmod[c] = s;
    }
}

// ---------------- segmented mean pool + final BN affine (warp per graph) ----
__global__ void pool_graph()
{
    int g = (blockIdx.x * blockDim.x + threadIdx.x) >> 5;
    int lane = threadIdx.x & 31;
    if (g >= GG) return;
    int beg = d_goff[g], end = d_goff[g + 1];
    float acc[12];
#pragma unroll
    for (int t = 0; t < 12; t++) acc[t] = 0.f;
    for (int n = beg; n < end; n++) {
        const __nv_bfloat162* hp = (const __nv_bfloat162*)&d_ayhi[(size_t)n * W3C];
        const __nv_bfloat162* lp = (const __nv_bfloat162*)&d_aylo[(size_t)n * W3C];
#pragma unroll
        for (int t = 0; t < 6; t++) {
            int p = lane + 32 * t;
            __nv_bfloat162 h = hp[p], l = lp[p];
            acc[t * 2 + 0] += __bfloat162float(h.x) + __bfloat162float(l.x);
            acc[t * 2 + 1] += __bfloat162float(h.y) + __bfloat162float(l.y);
        }
    }
    float inv = (end > beg) ? 1.f / (float)(end - beg) : 0.f;
#pragma unroll
    for (int t = 0; t < 6; t++) {
        int c = (lane + 32 * t) * 2;
        float m0 = acc[t * 2 + 0] * inv;
        float m1 = acc[t * 2 + 1] * inv;
        float o0 = (end > beg) ? m0 * d_scale[c] + d_shift[c] : 0.f;
        float o1 = (end > beg) ? m1 * d_scale[c + 1] + d_shift[c + 1] : 0.f;
        *(float2*)&d_gs[(size_t)g * W3C + c] = make_float2(o0, o1);
    }
}

// ---------------- log softmax -----------------------------------------------
__global__ void logsoftmax_kernel(float* __restrict__ out)
{
    int g = blockIdx.x * blockDim.x + threadIdx.x;
    if (g >= GG) return;
    float v[NCLS];
    float mx = -INFINITY;
#pragma unroll
    for (int c = 0; c < NCLS; c++) { v[c] = d_logits[g * NCLS + c]; mx = fmaxf(mx, v[c]); }
    float sum = 0.f;
#pragma unroll
    for (int c = 0; c < NCLS; c++) sum += expf(v[c] - mx);
    float lse = logf(sum) + mx;
#pragma unroll
    for (int c = 0; c < NCLS; c++) out[g * NCLS + c] = v[c] - lse;
}

// ---------------- host orchestration ----------------------------------------
extern "C" void kernel_launch(void* const* d_in, const int* in_sizes, int n_in,
                              void* d_out, int out_size)
{
    const float* x      = (const float*)d_in[0];
    const int*   ei     = (const int*)d_in[1];
    const int*   batch  = (const int*)d_in[2];
    const float* lin1_w = (const float*)d_in[3];
    const float* lin1_b = (const float*)d_in[4];
    const float* lin2_w = (const float*)d_in[5];
    const float* lin2_b = (const float*)d_in[6];
    const float* w0     = (const float*)d_in[7];
    const float* as0    = (const float*)d_in[8];
    const float* ad0    = (const float*)d_in[9];
    const float* b0     = (const float*)d_in[10];
    const float* wl     = (const float*)d_in[11];
    const float* asl    = (const float*)d_in[12];
    const float* adl    = (const float*)d_in[13];
    const float* bl     = (const float*)d_in[14];
    const float* gamma  = (const float*)d_in[15];
    const float* beta   = (const float*)d_in[16];
    const float* lin3_w = (const float*)d_in[17];
    const float* lin3_b = (const float*)d_in[18];
    const float* lin4_w = (const float*)d_in[19];
    const float* lin4_b = (const float*)d_in[20];

    float *bufB, *gs, *gh, *logits, *tmod, *scale, *bnsum, *bnsq;
    __nv_bfloat16 *axhi, *axlo, *ayhi, *aylo, *wthi, *wtlo;
    int *deg;
    cudaGetSymbolAddress((void**)&bufB, d_bufB);
    cudaGetSymbolAddress((void**)&gs, d_gs);
    cudaGetSymbolAddress((void**)&gh, d_gh);
    cudaGetSymbolAddress((void**)&logits, d_logits);
    cudaGetSymbolAddress((void**)&tmod, d_tmod);
    cudaGetSymbolAddress((void**)&scale, d_scale);
    cudaGetSymbolAddress((void**)&bnsum, d_bnsum);
    cudaGetSymbolAddress((void**)&bnsq, d_bnsq);
    cudaGetSymbolAddress((void**)&axhi, d_axhi);
    cudaGetSymbolAddress((void**)&axlo, d_axlo);
    cudaGetSymbolAddress((void**)&ayhi, d_ayhi);
    cudaGetSymbolAddress((void**)&aylo, d_aylo);
    cudaGetSymbolAddress((void**)&wthi, d_wthi);
    cudaGetSymbolAddress((void**)&wtlo, d_wtlo);
    cudaGetSymbolAddress((void**)&deg, d_deg);

    cudaFuncSetAttribute(mma_gemm, cudaFuncAttributeMaxDynamicSharedMemorySize, 81920);

    const int MT = (NN + 127) / 128;
    const int SMEM = 81920;

    // ---- stem ----
    {
        dim3 grid(2, MT);
        sgemm_pipe<<<grid, 256>>>(x, lin1_w, lin1_b, nullptr, NN, 256, FIN, 1, axhi, axlo);
    }
    transpose_split<<<(256 * 128 + 255) / 256, 256>>>(lin2_w, nullptr, 256, 128);
    {
        dim3 grid(1, MT);
        mma_gemm<<<grid, 256, SMEM>>>(axhi, axlo, wthi, wtlo, lin2_b, nullptr,
                                      NN, 128, 256, 1, ayhi, aylo);
    }
    transpose_split<<<(128 * 384 + 255) / 256, 256>>>(w0, nullptr, 128, 384);

    // ---- CSR build ----
    cudaMemsetAsync(deg, 0, sizeof(int) * NN);
    cudaMemsetAsync(bnsum, 0, sizeof(float) * W3C);    // once; bn_fold re-zeroes
    cudaMemsetAsync(bnsq, 0, sizeof(float) * W3C);
    deg_count<<<(ET + 255) / 256, 256>>>(ei);
    scan_block<<<NB1, 512>>>();
    scan_part<<<1, 256>>>();
    scan_add<<<(NN + 255) / 256, 256>>>();
    csr_scatter<<<(ET + 255) / 256, 256>>>(ei);

    for (int l = 0; l < NLAY; l++) {
        const float* a_s = l ? (asl + (size_t)(l - 1) * HH * HIDC) : as0;
        const float* a_d = l ? (adl + (size_t)(l - 1) * HH * HIDC) : ad0;
        const float* bi  = l ? (bl  + (size_t)(l - 1) * W3C)       : b0;
        int K = l ? W3C : HIDC;

        {
            dim3 grid(3, MT);
            mma_gemm<<<grid, 256, SMEM>>>(ayhi, aylo, wthi, wtlo,
                                          l ? tmod : nullptr, bufB,
                                          NN, W3C, K, 0, nullptr, nullptr);
        }
        gat_scores<<<(NN * 32 + 255) / 256, 256>>>(bufB, a_s, a_d);
        gat_aggregate<<<(NN * 32 + 255) / 256, 256>>>(bi);   // -> ayhi/aylo + BN stats
        const float* Wnext = (l < NLAY - 1) ? (wl + (size_t)l * W3C * W3C) : nullptr;
        bn_fold<<<1, W3C>>>(gamma + l * W3C, beta + l * W3C, Wnext);
        if (Wnext)
            transpose_split<<<(W3C * W3C + 255) / 256, 256>>>(Wnext, scale, W3C, W3C);
    }

    // ---- segmented global mean pool + final BN affine ----
    graph_off<<<(GG + 1 + 255) / 256, 256>>>(batch);
    pool_graph<<<(GG * 32 + 255) / 256, 256>>>();

    // ---- head ----
    {
        dim3 grid(1, (GG + 127) / 128);
        sgemm_pipe<<<grid, 256>>>(gs, lin3_w, lin3_b, gh, GG, HIDC, W3C, 1, nullptr, nullptr);
    }
    {
        dim3 blk(NCLS, 16);
        sgemm_small<<<(GG + 15) / 16, blk>>>(gh, lin4_w, lin4_b, logits, GG, NCLS, HIDC, 0);
    }
    logsoftmax_kernel<<<(GG + 255) / 256, 256>>>((float*)d_out);
}

// round 16
// speedup vs baseline: 1.5092x; 1.5092x over previous
#include <cuda_runtime.h>
#include <cuda_bf16.h>
#include <math.h>
#include <stdint.h>

#define NN 100000
#define EE 400000
#define ET (EE + NN)
#define GG 4000
#define FIN 32
#define HIDC 128
#define HH 3
#define W3C 384
#define NCLS 10
#define NLAY 4
#define NB1 ((NN + 511) / 512)

// ---------------- device scratch ----------------
__device__ float d_bufB[(size_t)NN * W3C];   // HW = x @ W (fp32, aggregation gather)
__device__ __nv_bfloat16 d_axhi[(size_t)NN * 256];
__device__ __nv_bfloat16 d_axlo[(size_t)NN * 256];
__device__ __nv_bfloat16 d_ayhi[(size_t)NN * W3C];
__device__ __nv_bfloat16 d_aylo[(size_t)NN * W3C];
__device__ __nv_bfloat16 d_wthi[W3C * W3C];
__device__ __nv_bfloat16 d_wtlo[W3C * W3C];
__device__ float d_es[NN * HH];
__device__ float d_ed[NN * HH];
__device__ float d_scale[W3C];
__device__ float d_shift[W3C];
__device__ float d_tmod[W3C];
__device__ float d_bnsum[W3C];
__device__ float d_bnsq[W3C];
__device__ float d_gs[(size_t)GG * W3C];
__device__ float d_gh[(size_t)GG * HIDC];
__device__ float d_logits[GG * NCLS];
// CSR + graph offsets
__device__ int d_deg[NN];
__device__ int d_off[NN + 1];
__device__ int d_cur[NN];
__device__ int d_csrc[ET];
__device__ int d_part[256];
__device__ int d_goff[GG + 1];

// ---------------- low-level helpers ----------------
__device__ __forceinline__ void cp16(void* dst, const void* src, int bytes)
{
    unsigned int d = (unsigned int)__cvta_generic_to_shared(dst);
    asm volatile("cp.async.ca.shared.global [%0], [%1], 16, %2;" :: "r"(d), "l"(src), "r"(bytes));
}

__device__ __forceinline__ uint32_t smem_u32(const void* p)
{
    uint32_t a;
    asm("{ .reg .u64 t; cvta.to.shared.u64 t, %1; cvt.u32.u64 %0, t; }" : "=r"(a) : "l"(p));
    return a;
}

__device__ __forceinline__ void ldsm4(uint32_t& r0, uint32_t& r1, uint32_t& r2, uint32_t& r3,
                                      uint32_t addr)
{
    asm volatile("ldmatrix.sync.aligned.m8n8.x4.shared.b16 {%0,%1,%2,%3}, [%4];"
                 : "=r"(r0), "=r"(r1), "=r"(r2), "=r"(r3) : "r"(addr));
}
__device__ __forceinline__ void ldsm2(uint32_t& r0, uint32_t& r1, uint32_t addr)
{
    asm volatile("ldmatrix.sync.aligned.m8n8.x2.shared.b16 {%0,%1}, [%2];"
                 : "=r"(r0), "=r"(r1) : "r"(addr));
}

__device__ __forceinline__ void mma16816(float* c, const uint32_t* a, const uint32_t* b)
{
    asm volatile(
        "mma.sync.aligned.m16n8k16.row.col.f32.bf16.bf16.f32 "
        "{%0,%1,%2,%3}, {%4,%5,%6,%7}, {%8,%9}, {%0,%1,%2,%3};"
        : "+f"(c[0]), "+f"(c[1]), "+f"(c[2]), "+f"(c[3])
        : "r"(a[0]), "r"(a[1]), "r"(a[2]), "r"(a[3]), "r"(b[0]), "r"(b[1]));
}

// ---------------- split-bf16 tensor-core GEMM (2 CTAs/SM) -------------------
__global__ void __launch_bounds__(256, 2) mma_gemm(
    const __nv_bfloat16* __restrict__ ahi, const __nv_bfloat16* __restrict__ alo,
    const __nv_bfloat16* __restrict__ bthi, const __nv_bfloat16* __restrict__ btlo,
    const float* __restrict__ bias, float* __restrict__ outF,
    int M, int N, int K, int relu,
    __nv_bfloat16* __restrict__ oh, __nv_bfloat16* __restrict__ ol)
{
    extern __shared__ char smem[];
    const int MAT = 10240;
    const int ST = 4 * MAT;
    int tid = threadIdx.x;
    int warp = tid >> 5, lane = tid & 31;
    int wm = warp >> 2, wn = warp & 3;
    int bm = blockIdx.y * 128, bn = blockIdx.x * 128;

    float acc[4][4][4];
#pragma unroll
    for (int i = 0; i < 4; i++)
#pragma unroll
        for (int j = 0; j < 4; j++)
#pragma unroll
            for (int r = 0; r < 4; r++) acc[i][j][r] = 0.f;

    const int nk = K >> 5;

    auto load_stage = [&](int s, int k0) {
        char* base = smem + s * ST;
#pragma unroll
        for (int t = 0; t < 8; t++) {
            int q = tid + t * 256;
            int sel = q >> 9;
            int r = q & 511;
            int row = r >> 2, ch = r & 3;
            char* dst = base + sel * MAT + row * 80 + ch * 16;
            if (sel < 2) {
                int gm = bm + row;
                const __nv_bfloat16* src = (sel == 0 ? ahi : alo);
                const __nv_bfloat16* p = src + (size_t)(gm < M ? gm : 0) * K + k0 + ch * 8;
                cp16(dst, p, gm < M ? 16 : 0);
            } else {
                int gn = bn + row;
                const __nv_bfloat16* src = (sel == 2 ? bthi : btlo);
                cp16(dst, src + (size_t)gn * K + k0 + ch * 8, 16);
            }
        }
        asm volatile("cp.async.commit_group;");
    };

    load_stage(0, 0);
    for (int t = 0; t < nk; t++) {
        if (t + 1 < nk) {
            load_stage((t + 1) & 1, (t + 1) << 5);
            asm volatile("cp.async.wait_group 1;");
        } else {
            asm volatile("cp.async.wait_group 0;");
        }
        __syncthreads();
        uint32_t sb = smem_u32(smem + (t & 1) * ST);
#pragma unroll
        for (int ks = 0; ks < 2; ks++) {
            int k0 = ks * 16;
            uint32_t af[2][4][4];
            uint32_t bf[2][4][2];
#pragma unroll
            for (int mt = 0; mt < 4; mt++) {
                int row = wm * 64 + mt * 16 + (lane & 15);
                uint32_t off = row * 80 + (k0 + (lane >> 4) * 8) * 2;
                ldsm4(af[0][mt][0], af[0][mt][1], af[0][mt][2], af[0][mt][3], sb + off);
                ldsm4(af[1][mt][0], af[1][mt][1], af[1][mt][2], af[1][mt][3], sb + MAT + off);
            }
#pragma unroll
            for (int nt = 0; nt < 4; nt++) {
                int row = wn * 32 + nt * 8 + (lane & 7);
                uint32_t off = row * 80 + (k0 + ((lane >> 3) & 1) * 8) * 2;
                ldsm2(bf[0][nt][0], bf[0][nt][1], sb + 2 * MAT + off);
                ldsm2(bf[1][nt][0], bf[1][nt][1], sb + 3 * MAT + off);
            }
#pragma unroll
            for (int mt = 0; mt < 4; mt++)
#pragma unroll
                for (int nt = 0; nt < 4; nt++) {
                    mma16816(acc[mt][nt], af[0][mt], bf[0][nt]);
                    mma16816(acc[mt][nt], af[0][mt], bf[1][nt]);
                    mma16816(acc[mt][nt], af[1][mt], bf[0][nt]);
                }
        }
        __syncthreads();
    }

    int g = lane >> 2, c2 = (lane & 3) * 2;
#pragma unroll
    for (int mt = 0; mt < 4; mt++) {
        int m0 = bm + wm * 64 + mt * 16 + g;
#pragma unroll
        for (int half = 0; half < 2; half++) {
            int m = m0 + half * 8;
            if (m >= M) continue;
#pragma unroll
            for (int nt = 0; nt < 4; nt++) {
                int n = bn + wn * 32 + nt * 8 + c2;
                float v0 = acc[mt][nt][half * 2 + 0];
                float v1 = acc[mt][nt][half * 2 + 1];
                if (bias) { v0 += bias[n]; v1 += bias[n + 1]; }
                if (relu) { v0 = fmaxf(v0, 0.f); v1 = fmaxf(v1, 0.f); }
                if (outF) *(float2*)&outF[(size_t)m * N + n] = make_float2(v0, v1);
                if (oh) {
                    __nv_bfloat16 h0 = __float2bfloat16(v0);
                    __nv_bfloat16 h1 = __float2bfloat16(v1);
                    __nv_bfloat162 hp; hp.x = h0; hp.y = h1;
                    __nv_bfloat162 lp;
                    lp.x = __float2bfloat16(v0 - __bfloat162float(h0));
                    lp.y = __float2bfloat16(v1 - __bfloat162float(h1));
                    *(__nv_bfloat162*)&oh[(size_t)m * N + n] = hp;
                    *(__nv_bfloat162*)&ol[(size_t)m * N + n] = lp;
                }
            }
        }
    }
}

// ---------------- transpose + scale + split weights -------------------------
__global__ void transpose_split(const float* __restrict__ W, const float* __restrict__ scale,
                                int K, int N)
{
    int idx = blockIdx.x * blockDim.x + threadIdx.x;
    if (idx >= K * N) return;
    int k = idx / N, n = idx - k * N;
    float v = W[idx];
    if (scale) v *= scale[k];
    __nv_bfloat16 h = __float2bfloat16(v);
    d_wthi[(size_t)n * K + k] = h;
    d_wtlo[(size_t)n * K + k] = __float2bfloat16(v - __bfloat162float(h));
}

// ---------------- f32x2 helpers ----------------
__device__ __forceinline__ unsigned long long pack2(float x, float y)
{
    unsigned long long r;
    asm("mov.b64 %0, {%1, %2};" : "=l"(r) : "r"(__float_as_uint(x)), "r"(__float_as_uint(y)));
    return r;
}
__device__ __forceinline__ unsigned long long fma2(unsigned long long a,
                                                   unsigned long long b,
                                                   unsigned long long c)
{
    unsigned long long d;
    asm("fma.rn.f32x2 %0, %1, %2, %3;" : "=l"(d) : "l"(a), "l"(b), "l"(c));
    return d;
}
__device__ __forceinline__ void unpack2(unsigned long long v, float& lo, float& hi)
{
    unsigned int a, b;
    asm("mov.b64 {%0, %1}, %2;" : "=r"(a), "=r"(b) : "l"(v));
    lo = __uint_as_float(a); hi = __uint_as_float(b);
}

// ---------------- pipelined fp32 SGEMM (stem lin1, head lin3) ---------------
__global__ void sgemm_pipe(const float* __restrict__ A, const float* __restrict__ B,
                           const float* __restrict__ bias, float* __restrict__ C,
                           int M, int Ncol, int K, int relu,
                           __nv_bfloat16* __restrict__ oh, __nv_bfloat16* __restrict__ ol)
{
    __shared__ float As[2][128][16];
    __shared__ float Bs[2][16][128];
    int tid = threadIdx.x;
    int tx = tid & 15, ty = tid >> 4;
    int bm = blockIdx.y * 128, bn = blockIdx.x * 128;

    unsigned long long acc[8][4];
#pragma unroll
    for (int i = 0; i < 8; i++)
#pragma unroll
        for (int j = 0; j < 4; j++) acc[i][j] = 0ull;

    const int nk = K >> 4;

    auto load_stage = [&](int s, int k0) {
#pragma unroll
        for (int t = 0; t < 2; t++) {
            int q = tid + t * 256;
            int m = q >> 2, kc = (q & 3) * 4;
            int gm = bm + m;
            int ok = (gm < M);
            const float* src = A + (size_t)(ok ? gm : 0) * K + k0 + kc;
            cp16(&As[s][m][kc], src, ok ? 16 : 0);
        }
#pragma unroll
        for (int t = 0; t < 2; t++) {
            int q = tid + t * 256;
            int kq = q >> 5, n4 = (q & 31) * 4;
            const float* src = B + (size_t)(k0 + kq) * Ncol + bn + n4;
            cp16(&Bs[s][kq][n4], src, 16);
        }
        asm volatile("cp.async.commit_group;");
    };

    load_stage(0, 0);
    for (int t = 0; t < nk; t++) {
        if (t + 1 < nk) {
            load_stage((t + 1) & 1, (t + 1) << 4);
            asm volatile("cp.async.wait_group 1;");
        } else {
            asm volatile("cp.async.wait_group 0;");
        }
        __syncthreads();
        int s = t & 1;
#pragma unroll
        for (int k4 = 0; k4 < 4; k4++) {
            float4 a[8];
#pragma unroll
            for (int i = 0; i < 8; i++)
                a[i] = *(const float4*)&As[s][ty + i * 16][k4 * 4];
#pragma unroll
            for (int kk = 0; kk < 4; kk++) {
                int k = k4 * 4 + kk;
                ulonglong2 b0 = *(const ulonglong2*)&Bs[s][k][tx * 8];
                ulonglong2 b1 = *(const ulonglong2*)&Bs[s][k][tx * 8 + 4];
                unsigned long long bp[4] = { b0.x, b0.y, b1.x, b1.y };
#pragma unroll
                for (int i = 0; i < 8; i++) {
                    float av = (&a[i].x)[kk];
                    unsigned long long ap = pack2(av, av);
#pragma unroll
                    for (int j = 0; j < 4; j++) acc[i][j] = fma2(ap, bp[j], acc[i][j]);
                }
            }
        }
        __syncthreads();
    }

#pragma unroll
    for (int i = 0; i < 8; i++) {
        int m = bm + ty + i * 16;
        if (m >= M) continue;
        float out[8];
#pragma unroll
        for (int j = 0; j < 4; j++) unpack2(acc[i][j], out[j * 2], out[j * 2 + 1]);
#pragma unroll
        for (int j = 0; j < 8; j++) {
            int n = bn + tx * 8 + j;
            float v = out[j];
            if (bias) v += bias[n];
            if (relu) v = fmaxf(v, 0.f);
            if (C) C[(size_t)m * Ncol + n] = v;
            if (oh) {
                __nv_bfloat16 h = __float2bfloat16(v);
                oh[(size_t)m * Ncol + n] = h;
                ol[(size_t)m * Ncol + n] = __float2bfloat16(v - __bfloat162float(h));
            }
        }
    }
}

// ---------------- small fallback GEMM ---------------------------------------
__global__ void sgemm_small(const float* __restrict__ A, const float* __restrict__ B,
                            const float* __restrict__ bias, float* __restrict__ C,
                            int M, int Ncol, int K, int relu)
{
    int m = blockIdx.x * blockDim.y + threadIdx.y;
    int n = threadIdx.x;
    if (m >= M || n >= Ncol) return;
    float s = 0.f;
    for (int k = 0; k < K; k++) s += A[(size_t)m * K + k] * B[(size_t)k * Ncol + n];
    if (bias) s += bias[n];
    if (relu) s = fmaxf(s, 0.f);
    C[(size_t)m * Ncol + n] = s;
}

// ---------------- CSR construction ------------------------------------------
__global__ void deg_count(const int* __restrict__ ei)
{
    int e = blockIdx.x * blockDim.x + threadIdx.x;
    if (e >= ET) return;
    int d = (e < EE) ? ei[EE + e] : (e - EE);
    atomicAdd(&d_deg[d], 1);
}

__global__ void scan_block()
{
    __shared__ int sh[512];
    int i = blockIdx.x * 512 + threadIdx.x;
    int v = (i < NN) ? d_deg[i] : 0;
    sh[threadIdx.x] = v;
    __syncthreads();
    for (int o = 1; o < 512; o <<= 1) {
        int t = (threadIdx.x >= o) ? sh[threadIdx.x - o] : 0;
        __syncthreads();
        sh[threadIdx.x] += t;
        __syncthreads();
    }
    if (i < NN) d_off[i] = sh[threadIdx.x] - v;
    if (threadIdx.x == 511) d_part[blockIdx.x] = sh[511];
}

__global__ void scan_part()
{
    __shared__ int sh[256];
    int t = threadIdx.x;
    int v = (t < NB1) ? d_part[t] : 0;
    sh[t] = v;
    __syncthreads();
    for (int o = 1; o < 256; o <<= 1) {
        int u = (t >= o) ? sh[t - o] : 0;
        __syncthreads();
        sh[t] += u;
        __syncthreads();
    }
    if (t < NB1) d_part[t] = sh[t] - v;
}

__global__ void scan_add()
{
    int i = blockIdx.x * blockDim.x + threadIdx.x;
    if (i < NN) {
        int v = d_off[i] + d_part[i >> 9];
        d_off[i] = v;
        d_cur[i] = v;
    }
    if (i == 0) d_off[NN] = ET;
}

__global__ void csr_scatter(const int* __restrict__ ei)
{
    int e = blockIdx.x * blockDim.x + threadIdx.x;
    if (e >= ET) return;
    int s = (e < EE) ? ei[e] : (e - EE);
    int d = (e < EE) ? ei[EE + e] : (e - EE);
    int pos = atomicAdd(&d_cur[d], 1);
    d_csrc[pos] = s;
}

// ---------------- graph offsets (batch is sorted) ---------------------------
__global__ void graph_off(const int* __restrict__ batch)
{
    int g = blockIdx.x * blockDim.x + threadIdx.x;
    if (g > GG) return;
    if (g == GG) { d_goff[GG] = NN; return; }
    int lo = 0, hi = NN;
    while (lo < hi) {
        int mid = (lo + hi) >> 1;
        if (batch[mid] < g) lo = mid + 1; else hi = mid;
    }
    d_goff[g] = lo;
}

// ---------------- GAT attention scores (warp per node, float4) --------------
__global__ void gat_scores(const float* __restrict__ HW,
                           const float* __restrict__ asrc,
                           const float* __restrict__ adst)
{
    int warp = (blockIdx.x * blockDim.x + threadIdx.x) >> 5;
    int lane = threadIdx.x & 31;
    if (warp >= NN) return;
    const float4* row = (const float4*)&HW[(size_t)warp * W3C];
    const float4* a4 = (const float4*)asrc;
    const float4* d4 = (const float4*)adst;
    float sa[3], sd[3];
#pragma unroll
    for (int t = 0; t < 3; t++) {
        float4 v = row[lane + 32 * t];
        float4 av = __ldg(&a4[lane + 32 * t]);
        float4 dv = __ldg(&d4[lane + 32 * t]);
        sa[t] = v.x * av.x + v.y * av.y + v.z * av.z + v.w * av.w;
        sd[t] = v.x * dv.x + v.y * dv.y + v.z * dv.z + v.w * dv.w;
    }
#pragma unroll
    for (int o = 16; o > 0; o >>= 1) {
#pragma unroll
        for (int t = 0; t < 3; t++) {
            sa[t] += __shfl_down_sync(0xffffffffu, sa[t], o);
            sd[t] += __shfl_down_sync(0xffffffffu, sd[t], o);
        }
    }
    if (lane == 0) {
#pragma unroll
        for (int t = 0; t < 3; t++) {
            d_es[warp * HH + t] = sa[t];
            d_ed[warp * HH + t] = sd[t];
        }
    }
}

// ---------------- fused segment softmax + aggregate + BN stats --------------
__global__ void gat_aggregate(const float* __restrict__ bias)
{
    __shared__ float bnS[W3C], bnQ[W3C];
    int tid = threadIdx.x;
    for (int c = tid; c < W3C; c += 256) { bnS[c] = 0.f; bnQ[c] = 0.f; }
    __syncthreads();

    int warp = (blockIdx.x * 256 + tid) >> 5;
    int lane = tid & 31;
    bool active = (warp < NN);

    if (active) {
        int beg = d_off[warp], end = d_off[warp + 1];
        int deg = end - beg;

        float edh0 = d_ed[warp * HH + 0];
        float edh1 = d_ed[warp * HH + 1];
        float edh2 = d_ed[warp * HH + 2];

        int sreg = 0;
        float xr0 = -INFINITY, xr1 = -INFINITY, xr2 = -INFINITY;
        if (lane < deg) {
            sreg = d_csrc[beg + lane];
            float a0 = d_es[sreg * HH + 0] + edh0;
            float a1 = d_es[sreg * HH + 1] + edh1;
            float a2 = d_es[sreg * HH + 2] + edh2;
            xr0 = (a0 > 0.f) ? a0 : 0.2f * a0;
            xr1 = (a1 > 0.f) ? a1 : 0.2f * a1;
            xr2 = (a2 > 0.f) ? a2 : 0.2f * a2;
        }
        float m0 = xr0, m1 = xr1, m2 = xr2;
        for (int j = beg + 32 + lane; j < end; j += 32) {
            int s = d_csrc[j];
            float a0 = d_es[s * HH + 0] + edh0; a0 = (a0 > 0.f) ? a0 : 0.2f * a0;
            float a1 = d_es[s * HH + 1] + edh1; a1 = (a1 > 0.f) ? a1 : 0.2f * a1;
            float a2 = d_es[s * HH + 2] + edh2; a2 = (a2 > 0.f) ? a2 : 0.2f * a2;
            m0 = fmaxf(m0, a0); m1 = fmaxf(m1, a1); m2 = fmaxf(m2, a2);
        }
#pragma unroll
        for (int o = 16; o > 0; o >>= 1) {
            m0 = fmaxf(m0, __shfl_xor_sync(0xffffffffu, m0, o));
            m1 = fmaxf(m1, __shfl_xor_sync(0xffffffffu, m1, o));
            m2 = fmaxf(m2, __shfl_xor_sync(0xffffffffu, m2, o));
        }

        float acc[3][4];
#pragma unroll
        for (int t = 0; t < 3; t++)
#pragma unroll
            for (int q = 0; q < 4; q++) acc[t][q] = 0.f;
        float s0 = 0.f, s1 = 0.f, s2 = 0.f;

        const float4* B4 = (const float4*)d_bufB;
        int n2 = deg < 32 ? deg : 32;
        for (int jj = 0; jj < n2; jj++) {
            int s = __shfl_sync(0xffffffffu, sreg, jj);
            float x0 = __shfl_sync(0xffffffffu, xr0, jj);
            float x1 = __shfl_sync(0xffffffffu, xr1, jj);
            float x2 = __shfl_sync(0xffffffffu, xr2, jj);
            float p0 = expf(x0 - m0), p1 = expf(x1 - m1), p2 = expf(x2 - m2);
            s0 += p0; s1 += p1; s2 += p2;
            const float4* row = B4 + (size_t)s * 96;
            float4 v0 = row[lane];
            float4 v1 = row[lane + 32];
            float4 v2 = row[lane + 64];
            acc[0][0] += p0 * v0.x; acc[0][1] += p0 * v0.y; acc[0][2] += p0 * v0.z; acc[0][3] += p0 * v0.w;
            acc[1][0] += p1 * v1.x; acc[1][1] += p1 * v1.y; acc[1][2] += p1 * v1.z; acc[1][3] += p1 * v1.w;
            acc[2][0] += p2 * v2.x; acc[2][1] += p2 * v2.y; acc[2][2] += p2 * v2.z; acc[2][3] += p2 * v2.w;
        }
        for (int j = beg + 32; j < end; j++) {
            int s = d_csrc[j];
            float a0 = d_es[s * HH + 0] + edh0; a0 = (a0 > 0.f) ? a0 : 0.2f * a0;
            float a1 = d_es[s * HH + 1] + edh1; a1 = (a1 > 0.f) ? a1 : 0.2f * a1;
            float a2 = d_es[s * HH + 2] + edh2; a2 = (a2 > 0.f) ? a2 : 0.2f * a2;
            float p0 = expf(a0 - m0), p1 = expf(a1 - m1), p2 = expf(a2 - m2);
            s0 += p0; s1 += p1; s2 += p2;
            const float4* row = B4 + (size_t)s * 96;
            float4 v0 = row[lane];
            float4 v1 = row[lane + 32];
            float4 v2 = row[lane + 64];
            acc[0][0] += p0 * v0.x; acc[0][1] += p0 * v0.y; acc[0][2] += p0 * v0.z; acc[0][3] += p0 * v0.w;
            acc[1][0] += p1 * v1.x; acc[1][1] += p1 * v1.y; acc[1][2] += p1 * v1.z; acc[1][3] += p1 * v1.w;
            acc[2][0] += p2 * v2.x; acc[2][1] += p2 * v2.y; acc[2][2] += p2 * v2.z; acc[2][3] += p2 * v2.w;
        }

        float inv[3] = { 1.f / s0, 1.f / s1, 1.f / s2 };
        const float4* b4 = (const float4*)bias;
        __nv_bfloat16* ohp = &d_ayhi[(size_t)warp * W3C];
        __nv_bfloat16* olp = &d_aylo[(size_t)warp * W3C];
#pragma unroll
        for (int t = 0; t < 3; t++) {
            float4 bv = __ldg(&b4[t * 32 + lane]);
            float v[4];
            v[0] = acc[t][0] * inv[t] + bv.x;
            v[1] = acc[t][1] * inv[t] + bv.y;
            v[2] = acc[t][2] * inv[t] + bv.z;
            v[3] = acc[t][3] * inv[t] + bv.w;
            int c = t * HIDC + 4 * lane;
#pragma unroll
            for (int q = 0; q < 4; q += 2) {
                __nv_bfloat16 h0 = __float2bfloat16(v[q]);
                __nv_bfloat16 h1 = __float2bfloat16(v[q + 1]);
                __nv_bfloat162 hp; hp.x = h0; hp.y = h1;
                __nv_bfloat162 lp;
                lp.x = __float2bfloat16(v[q] - __bfloat162float(h0));
                lp.y = __float2bfloat16(v[q + 1] - __bfloat162float(h1));
                *(__nv_bfloat162*)&ohp[c + q] = hp;
                *(__nv_bfloat162*)&olp[c + q] = lp;
            }
#pragma unroll
            for (int q = 0; q < 4; q++) {
                atomicAdd(&bnS[c + q], v[q]);
                atomicAdd(&bnQ[c + q], v[q] * v[q]);
            }
        }
    }

    __syncthreads();
    for (int c = tid; c < W3C; c += 256) {
        atomicAdd(&d_bnsum[c], bnS[c]);
        atomicAdd(&d_bnsq[c], bnQ[c]);
    }
}

// ---------------- BN finalize + zero-stats + fold shift into next bias ------
// W == nullptr for the last layer (no tmod needed).
__global__ void bn_fold(const float* __restrict__ gamma, const float* __restrict__ beta,
                        const float* __restrict__ W)
{
    __shared__ float sh[W3C];
    int c = threadIdx.x;  // 384
    float mu = d_bnsum[c] / (float)NN;
    float var = d_bnsq[c] / (float)NN - mu * mu;
    float sc = rsqrtf(var + 1e-5f) * gamma[c];
    float shf = beta[c] - mu * sc;
    d_scale[c] = sc;
    d_shift[c] = shf;
    d_bnsum[c] = 0.f;         // re-zero for next layer
    d_bnsq[c] = 0.f;
    sh[c] = shf;
    __syncthreads();
    if (W) {
        float s = 0.f;
        for (int k = 0; k < W3C; k++) s += sh[k] * W[(size_t)k * W3C + c];
        d_tmod[c] = s;
    }
}

// ---------------- segmented mean pool + final BN affine (warp per graph) ----
__global__ void pool_graph()
{
    int g = (blockIdx.x * blockDim.x + threadIdx.x) >> 5;
    int lane = threadIdx.x & 31;
    if (g >= GG) return;
    int beg = d_goff[g], end = d_goff[g + 1];
    float acc[12];
#pragma unroll
    for (int t = 0; t < 12; t++) acc[t] = 0.f;
    for (int n = beg; n < end; n++) {
        const __nv_bfloat162* hp = (const __nv_bfloat162*)&d_ayhi[(size_t)n * W3C];
        const __nv_bfloat162* lp = (const __nv_bfloat162*)&d_aylo[(size_t)n * W3C];
#pragma unroll
        for (int t = 0; t < 6; t++) {
            int p = lane + 32 * t;
            __nv_bfloat162 h = hp[p], l = lp[p];
            acc[t * 2 + 0] += __bfloat162float(h.x) + __bfloat162float(l.x);
            acc[t * 2 + 1] += __bfloat162float(h.y) + __bfloat162float(l.y);
        }
    }
    float inv = (end > beg) ? 1.f / (float)(end - beg) : 0.f;
#pragma unroll
    for (int t = 0; t < 6; t++) {
        int c = (lane + 32 * t) * 2;
        float m0 = acc[t * 2 + 0] * inv;
        float m1 = acc[t * 2 + 1] * inv;
        float o0 = (end > beg) ? m0 * d_scale[c] + d_shift[c] : 0.f;
        float o1 = (end > beg) ? m1 * d_scale[c + 1] + d_shift[c + 1] : 0.f;
        *(float2*)&d_gs[(size_t)g * W3C + c] = make_float2(o0, o1);
    }
}

// ---------------- log softmax -----------------------------------------------
__global__ void logsoftmax_kernel(float* __restrict__ out)
{
    int g = blockIdx.x * blockDim.x + threadIdx.x;
    if (g >= GG) return;
    float v[NCLS];
    float mx = -INFINITY;
#pragma unroll
    for (int c = 0; c < NCLS; c++) { v[c] = d_logits[g * NCLS + c]; mx = fmaxf(mx, v[c]); }
    float sum = 0.f;
#pragma unroll
    for (int c = 0; c < NCLS; c++) sum += expf(v[c] - mx);
    float lse = logf(sum) + mx;
#pragma unroll
    for (int c = 0; c < NCLS; c++) out[g * NCLS + c] = v[c] - lse;
}

// ---------------- host orchestration ----------------------------------------
extern "C" void kernel_launch(void* const* d_in, const int* in_sizes, int n_in,
                              void* d_out, int out_size)
{
    const float* x      = (const float*)d_in[0];
    const int*   ei     = (const int*)d_in[1];
    const int*   batch  = (const int*)d_in[2];
    const float* lin1_w = (const float*)d_in[3];
    const float* lin1_b = (const float*)d_in[4];
    const float* lin2_w = (const float*)d_in[5];
    const float* lin2_b = (const float*)d_in[6];
    const float* w0     = (const float*)d_in[7];
    const float* as0    = (const float*)d_in[8];
    const float* ad0    = (const float*)d_in[9];
    const float* b0     = (const float*)d_in[10];
    const float* wl     = (const float*)d_in[11];
    const float* asl    = (const float*)d_in[12];
    const float* adl    = (const float*)d_in[13];
    const float* bl     = (const float*)d_in[14];
    const float* gamma  = (const float*)d_in[15];
    const float* beta   = (const float*)d_in[16];
    const float* lin3_w = (const float*)d_in[17];
    const float* lin3_b = (const float*)d_in[18];
    const float* lin4_w = (const float*)d_in[19];
    const float* lin4_b = (const float*)d_in[20];

    float *bufB, *gs, *gh, *logits, *tmod, *scale, *bnsum, *bnsq;
    __nv_bfloat16 *axhi, *axlo, *ayhi, *aylo, *wthi, *wtlo;
    int *deg;
    cudaGetSymbolAddress((void**)&bufB, d_bufB);
    cudaGetSymbolAddress((void**)&gs, d_gs);
    cudaGetSymbolAddress((void**)&gh, d_gh);
    cudaGetSymbolAddress((void**)&logits, d_logits);
    cudaGetSymbolAddress((void**)&tmod, d_tmod);
    cudaGetSymbolAddress((void**)&scale, d_scale);
    cudaGetSymbolAddress((void**)&bnsum, d_bnsum);
    cudaGetSymbolAddress((void**)&bnsq, d_bnsq);
    cudaGetSymbolAddress((void**)&axhi, d_axhi);
    cudaGetSymbolAddress((void**)&axlo, d_axlo);
    cudaGetSymbolAddress((void**)&ayhi, d_ayhi);
    cudaGetSymbolAddress((void**)&aylo, d_aylo);
    cudaGetSymbolAddress((void**)&wthi, d_wthi);
    cudaGetSymbolAddress((void**)&wtlo, d_wtlo);
    cudaGetSymbolAddress((void**)&deg, d_deg);

    cudaFuncSetAttribute(mma_gemm, cudaFuncAttributeMaxDynamicSharedMemorySize, 81920);

    const int MT = (NN + 127) / 128;
    const int SMEM = 81920;

    // ---- stem ----
    {
        dim3 grid(2, MT);
        sgemm_pipe<<<grid, 256>>>(x, lin1_w, lin1_b, nullptr, NN, 256, FIN, 1, axhi, axlo);
    }
    transpose_split<<<(256 * 128 + 255) / 256, 256>>>(lin2_w, nullptr, 256, 128);
    {
        dim3 grid(1, MT);
        mma_gemm<<<grid, 256, SMEM>>>(axhi, axlo, wthi, wtlo, lin2_b, nullptr,
                                      NN, 128, 256, 1, ayhi, aylo);
    }
    transpose_split<<<(128 * 384 + 255) / 256, 256>>>(w0, nullptr, 128, 384);

    // ---- CSR build ----
    cudaMemsetAsync(deg, 0, sizeof(int) * NN);
    cudaMemsetAsync(bnsum, 0, sizeof(float) * W3C);    // once; bn_fold re-zeroes
    cudaMemsetAsync(bnsq, 0, sizeof(float) * W3C);
    deg_count<<<(ET + 255) / 256, 256>>>(ei);
    scan_block<<<NB1, 512>>>();
    scan_part<<<1, 256>>>();
    scan_add<<<(NN + 255) / 256, 256>>>();
    csr_scatter<<<(ET + 255) / 256, 256>>>(ei);

    for (int l = 0; l < NLAY; l++) {
        const float* a_s = l ? (asl + (size_t)(l - 1) * HH * HIDC) : as0;
        const float* a_d = l ? (adl + (size_t)(l - 1) * HH * HIDC) : ad0;
        const float* bi  = l ? (bl  + (size_t)(l - 1) * W3C)       : b0;
        int K = l ? W3C : HIDC;

        {
            dim3 grid(3, MT);
            mma_gemm<<<grid, 256, SMEM>>>(ayhi, aylo, wthi, wtlo,
                                          l ? tmod : nullptr, bufB,
                                          NN, W3C, K, 0, nullptr, nullptr);
        }
        gat_scores<<<(NN * 32 + 255) / 256, 256>>>(bufB, a_s, a_d);
        gat_aggregate<<<(NN * 32 + 255) / 256, 256>>>(bi);   // -> ayhi/aylo + BN stats
        const float* Wnext = (l < NLAY - 1) ? (wl + (size_t)l * W3C * W3C) : nullptr;
        bn_fold<<<1, W3C>>>(gamma + l * W3C, beta + l * W3C, Wnext);
        if (Wnext)
            transpose_split<<<(W3C * W3C + 255) / 256, 256>>>(Wnext, scale, W3C, W3C);
    }

    // ---- segmented global mean pool + final BN affine ----
    graph_off<<<(GG + 1 + 255) / 256, 256>>>(batch);
    pool_graph<<<(GG * 32 + 255) / 256, 256>>>();

    // ---- head ----
    {
        dim3 grid(1, (GG + 127) / 128);
        sgemm_pipe<<<grid, 256>>>(gs, lin3_w, lin3_b, gh, GG, HIDC, W3C, 1, nullptr, nullptr);
    }
    {
        dim3 blk(NCLS, 16);
        sgemm_small<<<(GG + 15) / 16, blk>>>(gh, lin4_w, lin4_b, logits, GG, NCLS, HIDC, 0);
    }
    logsoftmax_kernel<<<(GG + 255) / 256, 256>>>((float*)d_out);
}